// round 3
// baseline (speedup 1.0000x reference)
#include <cuda_runtime.h>
#include <cuda_bf16.h>
#include <cstdint>

// Problem constants
#define N_STREAMS 8
#define D_MODEL   2048
#define NS        16
#define N_SKEW    120
#define KPAD      128
#define TOKENS    8192
#define TPC       16
#define THREADS   512
#define NTILES    (TOKENS / TPC)      // 512
#define DP_TOTAL  (D_MODEL / 2)       // 1024

// Chunked pipeline
#define NC   16                       // chunks
#define DC   (D_MODEL / NC)           // 128 floats per chunk per token
#define DC4  (DC / 4)                 // 32 float4 per chunk per token
#define DPC  (DC / 2)                 // 64 dpairs per chunk

// W transposed + f32x2-packed: g_Wt2[dp*KPAD + k] = (W[k][2dp], W[k][2dp+1]); 0 for k>=120
__device__ float2 g_Wt2[DP_TOTAL * KPAD];   // 1 MB

__global__ void prep_wt_kernel(const float* __restrict__ W) {
    int id = blockIdx.x * blockDim.x + threadIdx.x;
    int dp = id & (DP_TOTAL - 1);
    int k  = id >> 10;
    float2 v = make_float2(0.f, 0.f);
    if (k < N_SKEW) {
        v.x = W[k * D_MODEL + 2 * dp];
        v.y = W[k * D_MODEL + 2 * dp + 1];
    }
    g_Wt2[dp * KPAD + k] = v;
}

__device__ __forceinline__ void fma2(unsigned long long& acc,
                                     unsigned long long a,
                                     unsigned long long b) {
    asm("fma.rn.f32x2 %0, %1, %2, %0;" : "+l"(acc) : "l"(a), "l"(b));
}

extern "C" __global__ void __launch_bounds__(THREADS, 1)
gomhc_fused_kernel(const float* __restrict__ streams,
                   const float* __restrict__ bias,
                   float* __restrict__ out) {
    __shared__ float xs[2][TPC * DC];   // double-buffered mean tile: 2 x 8 KB
    __shared__ float zs[TPC * KPAD];    // 8 KB

    const int tid  = threadIdx.x;
    const int tile = blockIdx.x;

    for (int i = tid; i < TPC * KPAD; i += THREADS) zs[i] = 0.f;

    // ---- load mapping: one (token, float4-slot) per thread ----
    const int lt = tid >> 5;            // token 0..15
    const int lf = tid & 31;            // float4 slot 0..31 within chunk
    const float4* sbase = reinterpret_cast<const float4*>(streams)
                        + (size_t)tile * TPC * (N_STREAMS * D_MODEL / 4)
                        + lt * (N_STREAMS * D_MODEL / 4) + lf;
    // per-stream stride = D_MODEL/4 = 512 float4; chunk offset = c*DC4

    // ---- GEMV mapping ----
    const int kg   = tid & 63;          // k = 2kg, 2kg+1
    const int rest = tid >> 6;
    const int tg   = rest & 1;          // token half (8 tokens)
    const int ds   = rest >> 1;         // d quarter within chunk (16 dp)

    unsigned long long acc0[8], acc1[8];
    #pragma unroll
    for (int t = 0; t < 8; t++) { acc0[t] = 0ull; acc1[t] = 0ull; }

    // prologue: issue chunk-0 loads
    float4 R[N_STREAMS];
    #pragma unroll
    for (int n = 0; n < N_STREAMS; n++)
        R[n] = sbase[n * (D_MODEL / 4)];

    #pragma unroll 1
    for (int c = 0; c < NC; c++) {
        // reduce streams -> mean, store to xs[c&1]
        #pragma unroll
        for (int s = N_STREAMS / 2; s > 0; s >>= 1)
            #pragma unroll
            for (int n = 0; n < s; n++) {
                R[n].x += R[n + s].x; R[n].y += R[n + s].y;
                R[n].z += R[n + s].z; R[n].w += R[n + s].w;
            }
        R[0].x *= 0.125f; R[0].y *= 0.125f; R[0].z *= 0.125f; R[0].w *= 0.125f;
        reinterpret_cast<float4*>(xs[c & 1])[lt * DC4 + lf] = R[0];

        __syncthreads();

        // issue next chunk's loads (fly behind the GEMV below)
        if (c + 1 < NC) {
            const float4* nb = sbase + (c + 1) * DC4;
            #pragma unroll
            for (int n = 0; n < N_STREAMS; n++)
                R[n] = nb[n * (D_MODEL / 4)];
        }

        // GEMV slice on this chunk
        {
            const float* xb = xs[c & 1] + tg * 8 * DC + 2 * (ds * 16);
            const ulonglong2* __restrict__ wp =
                reinterpret_cast<const ulonglong2*>(g_Wt2)
                + (size_t)(c * DPC + ds * 16) * (KPAD / 2) + kg;
            #pragma unroll 4
            for (int j = 0; j < 16; j++) {
                ulonglong2 w = wp[j * (KPAD / 2)];
                const float* xr = xb + 2 * j;
                #pragma unroll
                for (int t = 0; t < 8; t++) {
                    unsigned long long x2 =
                        *reinterpret_cast<const unsigned long long*>(xr + t * DC);
                    fma2(acc0[t], w.x, x2);
                    fma2(acc1[t], w.y, x2);
                }
            }
        }
        // single sync per iter is safe: buffer written again only at c+2,
        // and every warp passes sync(c+1) only after finishing GEMV(c).
    }

    // ---- reduce 4 d-quarter partials via shared atomics ----
    #pragma unroll
    for (int t = 0; t < 8; t++) {
        float2 a = *reinterpret_cast<float2*>(&acc0[t]);
        float2 b = *reinterpret_cast<float2*>(&acc1[t]);
        atomicAdd(&zs[(tg * 8 + t) * KPAD + 2 * kg    ], a.x + a.y);
        atomicAdd(&zs[(tg * 8 + t) * KPAD + 2 * kg + 1], b.x + b.y);
    }
    __syncthreads();

    for (int i = tid; i < TPC * N_SKEW; i += THREADS) {
        int t = i / N_SKEW, k = i - t * N_SKEW;
        zs[t * KPAD + k] += bias[k];
    }
    __syncthreads();

    // ---- Phase C: Cayley solve + block Frobenius, one warp per token ----
    {
        const int warp = tid >> 5;
        const int lane = tid & 31;
        const int r    = lane & 15;
        const float* zt = zs + warp * KPAD;

        float m[32];
        #pragma unroll
        for (int cc = 0; cc < NS; cc++) {
            float a = 0.f;
            if (cc > r)      a =  zt[(r * (31 - r)) / 2 + (cc - r - 1)];
            else if (cc < r) a = -zt[(cc * (31 - cc)) / 2 + (r - cc - 1)];
            float diag = (cc == r) ? 1.f : 0.f;
            m[cc]      = diag + a;
            m[16 + cc] = diag - a;
        }

        const unsigned mask = 0xffffffffu;
        #pragma unroll
        for (int i = 0; i < NS; i++) {
            float piv[32];
            #pragma unroll
            for (int k = 0; k < 32; k++) piv[k] = __shfl_sync(mask, m[k], i);
            float rp = 1.0f / piv[i];
            if (r == i) {
                #pragma unroll
                for (int k = 0; k < 32; k++) m[k] *= rp;
            } else {
                float f = m[i] * rp;
                #pragma unroll
                for (int k = 0; k < 32; k++) m[k] = fmaf(-f, piv[k], m[k]);
            }
        }

        float hq[8];
        #pragma unroll
        for (int q = 0; q < 8; q++) {
            float q0 = m[16 + 2 * q], q1 = m[16 + 2 * q + 1];
            hq[q] = q0 * q0 + q1 * q1;
        }
        #pragma unroll
        for (int q = 0; q < 8; q++)
            hq[q] += __shfl_xor_sync(mask, hq[q], 1);

        if (lane < 16 && !(r & 1)) {
            const int tok = tile * TPC + warp;
            float* o = out + (size_t)tok * 64 + (r >> 1) * 8;
            #pragma unroll
            for (int q = 0; q < 8; q++) o[q] = 0.5f * hq[q];
        }
    }
}

extern "C" void kernel_launch(void* const* d_in, const int* in_sizes, int n_in,
                              void* d_out, int out_size) {
    const float* streams = (const float*)d_in[0];
    const float* W       = (const float*)d_in[1];
    const float* b       = (const float*)d_in[2];
    float* out = (float*)d_out;

    prep_wt_kernel<<<(DP_TOTAL * KPAD) / 256, 256>>>(W);
    gomhc_fused_kernel<<<NTILES, THREADS>>>(streams, b, out);
}